// round 4
// baseline (speedup 1.0000x reference)
#include <cuda_runtime.h>

#define THREADS 256
#define SB 8           // samples per CTA
#define NQ 7           // quantities per neuron: h, J0..2, T0..2
#define DH 256         // hidden width

// ---- packed f32x2 helpers (Blackwell FFMA2: 2 fp32 FMAs per instruction) ----
__device__ __forceinline__ unsigned long long bc2(float a) {
    unsigned long long r;
    asm("mov.b64 %0, {%1, %1};" : "=l"(r) : "f"(a));
    return r;
}
__device__ __forceinline__ void fma2(unsigned long long& d, unsigned long long a,
                                     unsigned long long b) {
    asm("fma.rn.f32x2 %0, %1, %2, %0;" : "+l"(d) : "l"(a), "l"(b));
}
__device__ __forceinline__ void up2(unsigned long long v, float& lo, float& hi) {
    asm("mov.b64 {%0, %1}, %2;" : "=f"(lo), "=f"(hi) : "l"(v));
}

// State layout in dynamic smem: S[q][i][s], q in [0,7), i in [0,256), s in [0,8)
#define SIDX(q, i, s) (((q) * DH + (i)) * SB + (s))

__global__ void __launch_bounds__(THREADS, 2) pinn_fwd2_kernel(
    const float* __restrict__ x,
    const float* __restrict__ W0, const float* __restrict__ b0,
    const float* __restrict__ W1, const float* __restrict__ b1,
    const float* __restrict__ W2, const float* __restrict__ b2,
    const float* __restrict__ W3, const float* __restrict__ b3,
    const float* __restrict__ W4, const float* __restrict__ b4,
    const float* __restrict__ lb, const float* __restrict__ ub,
    float* __restrict__ out, int N)
{
    extern __shared__ float S[];          // NQ*DH*SB floats = 57344 B
    __shared__ float w4s[DH * 2];
    __shared__ float b4s[2];

    const int tid = threadIdx.x;          // one neuron per thread (0..255)
    const int s0  = blockIdx.x * SB;

    // Stage final-layer weights (consumed after last barrier).
    for (int i = tid; i < DH * 2; i += THREADS) w4s[i] = W4[i];
    if (tid < 2) b4s[tid] = b4[tid];

    // Input normalization constants
    float lbv[3], sk[3];
#pragma unroll
    for (int k = 0; k < 3; k++) {
        lbv[k] = lb[k];
        sk[k]  = 2.0f / (ub[k] - lb[k]);
    }

    // ---------------- Layer 0: 3 -> 256 ----------------
    // dH0[i]/dx_k = sk[k] * delta_ik ; T input = 0
    {
        const int j = tid;
        float w[3];
#pragma unroll
        for (int k = 0; k < 3; k++) w[k] = W0[k * DH + j];
        const float bj = b0[j];
        float zj[3], Szl = 0.0f;
#pragma unroll
        for (int k = 0; k < 3; k++) { zj[k] = w[k] * sk[k]; Szl += zj[k]; }
#pragma unroll
        for (int s = 0; s < SB; s++) {
            float xn[3];
#pragma unroll
            for (int k = 0; k < 3; k++)
                xn[k] = sk[k] * (x[(s0 + s) * 3 + k] - lbv[k]) - 1.0f;
            float z = bj + w[0] * xn[0] + w[1] * xn[1] + w[2] * xn[2];
            float t = tanhf(z);
            float g = 1.0f - t * t;
            float u = -2.0f * t * g * Szl;
            S[SIDX(0, j, s)] = t;
#pragma unroll
            for (int k = 0; k < 3; k++) {
                S[SIDX(1 + k, j, s)] = g * zj[k];
                S[SIDX(4 + k, j, s)] = u * zj[k];
            }
        }
    }
    __syncthreads();

    // ---------------- Hidden layers 1..3: 256 -> 256 ----------------
    for (int L = 0; L < 3; L++) {
        const float* __restrict__ W = (L == 0) ? W1 : ((L == 1) ? W2 : W3);
        const float* __restrict__ b = (L == 0) ? b1 : ((L == 1) ? b2 : b3);

        unsigned long long acc[NQ][4];
        {
            unsigned long long bb = bc2(b[tid]);
#pragma unroll
            for (int p = 0; p < 4; p++) acc[0][p] = bb;
#pragma unroll
            for (int q = 1; q < NQ; q++)
#pragma unroll
                for (int p = 0; p < 4; p++) acc[q][p] = 0ull;
        }

#pragma unroll 4
        for (int i = 0; i < DH; i++) {
            unsigned long long w = bc2(W[i * DH + tid]);
#pragma unroll
            for (int q = 0; q < NQ; q++) {
                const ulonglong2* p =
                    reinterpret_cast<const ulonglong2*>(&S[SIDX(q, i, 0)]);
                ulonglong2 v0 = p[0];
                ulonglong2 v1 = p[1];
                fma2(acc[q][0], w, v0.x);
                fma2(acc[q][1], w, v0.y);
                fma2(acc[q][2], w, v1.x);
                fma2(acc[q][3], w, v1.y);
            }
        }
        __syncthreads();   // everyone done reading old state

        const int j = tid;
#pragma unroll
        for (int p = 0; p < 4; p++) {
            float zh[2], zj0[2], zj1[2], zj2[2], zt0[2], zt1[2], zt2[2];
            up2(acc[0][p], zh[0], zh[1]);
            up2(acc[1][p], zj0[0], zj0[1]);
            up2(acc[2][p], zj1[0], zj1[1]);
            up2(acc[3][p], zj2[0], zj2[1]);
            up2(acc[4][p], zt0[0], zt0[1]);
            up2(acc[5][p], zt1[0], zt1[1]);
            up2(acc[6][p], zt2[0], zt2[1]);
#pragma unroll
            for (int e = 0; e < 2; e++) {
                const int s = p * 2 + e;
                float t  = tanhf(zh[e]);
                float g  = 1.0f - t * t;
                float Sz = zj0[e] + zj1[e] + zj2[e];
                float u  = -2.0f * t * g * Sz;
                S[SIDX(0, j, s)] = t;
                S[SIDX(1, j, s)] = g * zj0[e];
                S[SIDX(2, j, s)] = g * zj1[e];
                S[SIDX(3, j, s)] = g * zj2[e];
                S[SIDX(4, j, s)] = u * zj0[e] + g * zt0[e];
                S[SIDX(5, j, s)] = u * zj1[e] + g * zt1[e];
                S[SIDX(6, j, s)] = u * zj2[e] + g * zt2[e];
            }
        }
        __syncthreads();   // new state visible for next layer
    }

    // ---------------- Final layer: 256 -> 2 (linear) ----------------
    // 7 quantities x 2 outputs x 8 samples = 112 dot products of length 256.
    if (tid < NQ * 2 * SB) {
        const int q = tid % NQ;
        const int o = (tid / NQ) & 1;
        const int s = tid / (NQ * 2);
        float sum = 0.0f;
#pragma unroll 8
        for (int i = 0; i < DH; i++)
            sum += w4s[i * 2 + o] * S[SIDX(q, i, s)];
        const int n = s0 + s;
        if (q == 0) {
            out[n * 2 + o] = sum + b4s[o];                    // out[N,2]
        } else if (q < 4) {
            out[2 * N + o * 3 * N + n * 3 + (q - 1)] = sum;   // partials_1[2,N,3]
        } else {
            out[8 * N + o * 3 * N + n * 3 + (q - 4)] = sum;   // partials_2[2,N,3]
        }
    }
}

extern "C" void kernel_launch(void* const* d_in, const int* in_sizes, int n_in,
                              void* d_out, int out_size)
{
    const float* x  = (const float*)d_in[0];
    const float* W0 = (const float*)d_in[1];
    const float* b0 = (const float*)d_in[2];
    const float* W1 = (const float*)d_in[3];
    const float* b1 = (const float*)d_in[4];
    const float* W2 = (const float*)d_in[5];
    const float* b2 = (const float*)d_in[6];
    const float* W3 = (const float*)d_in[7];
    const float* b3 = (const float*)d_in[8];
    const float* W4 = (const float*)d_in[9];
    const float* b4 = (const float*)d_in[10];
    const float* lb = (const float*)d_in[11];
    const float* ub = (const float*)d_in[12];
    float* out = (float*)d_out;

    const int N = in_sizes[0] / 3;          // 32768
    const int smem = NQ * DH * SB * (int)sizeof(float);   // 57344 B

    cudaFuncSetAttribute(pinn_fwd2_kernel,
                         cudaFuncAttributeMaxDynamicSharedMemorySize, smem);

    pinn_fwd2_kernel<<<N / SB, THREADS, smem>>>(
        x, W0, b0, W1, b1, W2, b2, W3, b3, W4, b4, lb, ub, out, N);
}

// round 6
// speedup vs baseline: 1.5749x; 1.5749x over previous
#include <cuda_runtime.h>

#define THREADS 128
#define SB 8           // samples per CTA
#define NQ 7           // quantities per neuron: h, J0..2, T0..2
#define DH 256         // hidden width
#define NN 4           // neurons per thread
#define SS 4           // samples per thread

// ---- packed f32x2 helpers (Blackwell FFMA2: 2 fp32 FMAs per instruction) ----
__device__ __forceinline__ unsigned long long bc2(float a) {
    unsigned long long r;
    asm("mov.b64 %0, {%1, %1};" : "=l"(r) : "f"(a));
    return r;
}
__device__ __forceinline__ void fma2(unsigned long long& d, unsigned long long a,
                                     unsigned long long b) {
    asm("fma.rn.f32x2 %0, %1, %2, %0;" : "+l"(d) : "l"(a), "l"(b));
}
__device__ __forceinline__ void up2(unsigned long long v, float& lo, float& hi) {
    asm("mov.b64 {%0, %1}, %2;" : "=f"(lo), "=f"(hi) : "l"(v));
}

// State layout in dynamic smem: S[q][i][s], q in [0,7), i in [0,256), s in [0,8)
#define SIDX(q, i, s) (((q) * DH + (i)) * SB + (s))

__global__ void __launch_bounds__(THREADS, 2) pinn_fwd2_kernel(
    const float* __restrict__ x,
    const float* __restrict__ W0, const float* __restrict__ b0,
    const float* __restrict__ W1, const float* __restrict__ b1,
    const float* __restrict__ W2, const float* __restrict__ b2,
    const float* __restrict__ W3, const float* __restrict__ b3,
    const float* __restrict__ W4, const float* __restrict__ b4,
    const float* __restrict__ lb, const float* __restrict__ ub,
    float* __restrict__ out, int N)
{
    extern __shared__ float S[];          // NQ*DH*SB floats = 57344 B
    __shared__ float w4s[DH * 2];
    __shared__ float b4s[2];

    const int tid = threadIdx.x;
    const int g   = tid & 63;             // neuron group: this thread owns j = nn*64 + g
    const int h   = tid >> 6;             // sample half: samples h*4 .. h*4+3
    const int s0  = blockIdx.x * SB;

    // Stage final-layer weights (consumed after last barrier).
    for (int i = tid; i < DH * 2; i += THREADS) w4s[i] = W4[i];
    if (tid < 2) b4s[tid] = b4[tid];

    // Input normalization constants
    float lbv[3], sk[3];
#pragma unroll
    for (int k = 0; k < 3; k++) {
        lbv[k] = lb[k];
        sk[k]  = 2.0f / (ub[k] - lb[k]);
    }

    // ---------------- Layer 0: 3 -> 256 ----------------
    // dH0[i]/dx_k = sk[k] * delta_ik ; T input = 0
    {
        float xn[SS][3];
#pragma unroll
        for (int ss = 0; ss < SS; ss++) {
            const int s = h * SS + ss;
#pragma unroll
            for (int k = 0; k < 3; k++)
                xn[ss][k] = sk[k] * (x[(s0 + s) * 3 + k] - lbv[k]) - 1.0f;
        }
#pragma unroll
        for (int nn = 0; nn < NN; nn++) {
            const int j = nn * 64 + g;
            float w[3];
#pragma unroll
            for (int k = 0; k < 3; k++) w[k] = W0[k * DH + j];
            const float bj = b0[j];
            float zj[3], Szl = 0.0f;
#pragma unroll
            for (int k = 0; k < 3; k++) { zj[k] = w[k] * sk[k]; Szl += zj[k]; }
            float o[NQ][SS];
#pragma unroll
            for (int ss = 0; ss < SS; ss++) {
                float z = bj + w[0] * xn[ss][0] + w[1] * xn[ss][1] + w[2] * xn[ss][2];
                float t = tanhf(z);
                float gg = 1.0f - t * t;
                float u = -2.0f * t * gg * Szl;
                o[0][ss] = t;
#pragma unroll
                for (int k = 0; k < 3; k++) {
                    o[1 + k][ss] = gg * zj[k];
                    o[4 + k][ss] = u * zj[k];
                }
            }
#pragma unroll
            for (int q = 0; q < NQ; q++)
                *reinterpret_cast<float4*>(&S[SIDX(q, j, h * SS)]) =
                    make_float4(o[q][0], o[q][1], o[q][2], o[q][3]);
        }
    }
    __syncthreads();

    // ---------------- Hidden layers 1..3: 256 -> 256 ----------------
    for (int L = 0; L < 3; L++) {
        const float* __restrict__ W = (L == 0) ? W1 : ((L == 1) ? W2 : W3);
        const float* __restrict__ b = (L == 0) ? b1 : ((L == 1) ? b2 : b3);

        unsigned long long acc[NQ][NN][2];   // [quantity][neuron][sample-pair]
#pragma unroll
        for (int nn = 0; nn < NN; nn++) {
            unsigned long long bb = bc2(b[nn * 64 + g]);
            acc[0][nn][0] = bb; acc[0][nn][1] = bb;
#pragma unroll
            for (int q = 1; q < NQ; q++) { acc[q][nn][0] = 0ull; acc[q][nn][1] = 0ull; }
        }

        // software-pipelined prefetch (1 iteration deep)
        float wn[NN];
        ulonglong2 vn[NQ];
#pragma unroll
        for (int nn = 0; nn < NN; nn++) wn[nn] = W[nn * 64 + g];
#pragma unroll
        for (int q = 0; q < NQ; q++)
            vn[q] = *reinterpret_cast<const ulonglong2*>(&S[SIDX(q, 0, h * SS)]);

#pragma unroll 4
        for (int i = 0; i < DH; i++) {
            float wc[NN];
            ulonglong2 vc[NQ];
#pragma unroll
            for (int nn = 0; nn < NN; nn++) wc[nn] = wn[nn];
#pragma unroll
            for (int q = 0; q < NQ; q++) vc[q] = vn[q];

            const int in = (i + 1) & (DH - 1);   // clamp: last prefetch reads row 0 (discarded)
#pragma unroll
            for (int nn = 0; nn < NN; nn++) wn[nn] = W[in * DH + nn * 64 + g];
#pragma unroll
            for (int q = 0; q < NQ; q++)
                vn[q] = *reinterpret_cast<const ulonglong2*>(&S[SIDX(q, in, h * SS)]);

            unsigned long long w2[NN];
#pragma unroll
            for (int nn = 0; nn < NN; nn++) w2[nn] = bc2(wc[nn]);
#pragma unroll
            for (int q = 0; q < NQ; q++)
#pragma unroll
                for (int nn = 0; nn < NN; nn++) {
                    fma2(acc[q][nn][0], w2[nn], vc[q].x);
                    fma2(acc[q][nn][1], w2[nn], vc[q].y);
                }
        }
        __syncthreads();   // everyone done reading old state

#pragma unroll
        for (int nn = 0; nn < NN; nn++) {
            const int j = nn * 64 + g;
            float zh[SS], zj0[SS], zj1[SS], zj2[SS], zt0[SS], zt1[SS], zt2[SS];
#pragma unroll
            for (int p = 0; p < 2; p++) {
                up2(acc[0][nn][p], zh[2 * p],  zh[2 * p + 1]);
                up2(acc[1][nn][p], zj0[2 * p], zj0[2 * p + 1]);
                up2(acc[2][nn][p], zj1[2 * p], zj1[2 * p + 1]);
                up2(acc[3][nn][p], zj2[2 * p], zj2[2 * p + 1]);
                up2(acc[4][nn][p], zt0[2 * p], zt0[2 * p + 1]);
                up2(acc[5][nn][p], zt1[2 * p], zt1[2 * p + 1]);
                up2(acc[6][nn][p], zt2[2 * p], zt2[2 * p + 1]);
            }
            float o[NQ][SS];
#pragma unroll
            for (int e = 0; e < SS; e++) {
                float t  = tanhf(zh[e]);
                float gg = 1.0f - t * t;
                float Sz = zj0[e] + zj1[e] + zj2[e];
                float u  = -2.0f * t * gg * Sz;
                o[0][e] = t;
                o[1][e] = gg * zj0[e];
                o[2][e] = gg * zj1[e];
                o[3][e] = gg * zj2[e];
                o[4][e] = u * zj0[e] + gg * zt0[e];
                o[5][e] = u * zj1[e] + gg * zt1[e];
                o[6][e] = u * zj2[e] + gg * zt2[e];
            }
#pragma unroll
            for (int q = 0; q < NQ; q++)
                *reinterpret_cast<float4*>(&S[SIDX(q, j, h * SS)]) =
                    make_float4(o[q][0], o[q][1], o[q][2], o[q][3]);
        }
        __syncthreads();   // new state visible for next layer
    }

    // ---------------- Final layer: 256 -> 2 (linear) ----------------
    // 7 quantities x 2 outputs x 8 samples = 112 dot products of length 256.
    if (tid < NQ * 2 * SB) {
        const int q = tid % NQ;
        const int o = (tid / NQ) & 1;
        const int s = tid / (NQ * 2);
        float sum = 0.0f;
#pragma unroll 8
        for (int i = 0; i < DH; i++)
            sum += w4s[i * 2 + o] * S[SIDX(q, i, s)];
        const int n = s0 + s;
        if (q == 0) {
            out[n * 2 + o] = sum + b4s[o];                    // out[N,2]
        } else if (q < 4) {
            out[2 * N + o * 3 * N + n * 3 + (q - 1)] = sum;   // partials_1[2,N,3]
        } else {
            out[8 * N + o * 3 * N + n * 3 + (q - 4)] = sum;   // partials_2[2,N,3]
        }
    }
}

extern "C" void kernel_launch(void* const* d_in, const int* in_sizes, int n_in,
                              void* d_out, int out_size)
{
    const float* x  = (const float*)d_in[0];
    const float* W0 = (const float*)d_in[1];
    const float* b0 = (const float*)d_in[2];
    const float* W1 = (const float*)d_in[3];
    const float* b1 = (const float*)d_in[4];
    const float* W2 = (const float*)d_in[5];
    const float* b2 = (const float*)d_in[6];
    const float* W3 = (const float*)d_in[7];
    const float* b3 = (const float*)d_in[8];
    const float* W4 = (const float*)d_in[9];
    const float* b4 = (const float*)d_in[10];
    const float* lb = (const float*)d_in[11];
    const float* ub = (const float*)d_in[12];
    float* out = (float*)d_out;

    const int N = in_sizes[0] / 3;          // 32768
    const int smem = NQ * DH * SB * (int)sizeof(float);   // 57344 B

    cudaFuncSetAttribute(pinn_fwd2_kernel,
                         cudaFuncAttributeMaxDynamicSharedMemorySize, smem);

    pinn_fwd2_kernel<<<N / SB, THREADS, smem>>>(
        x, W0, b0, W1, b1, W2, b2, W3, b3, W4, b4, lb, ub, out, N);
}

// round 8
// speedup vs baseline: 3.4491x; 2.1900x over previous
#include <cuda_runtime.h>
#include <cuda_bf16.h>
#include <cstdint>

// ============================================================
// PINN fwd + 1st/2nd derivatives via mma.sync (HMMA) bf16 hi/lo
//   CTA: 16 samples. State S[i][c] bf16 hi/lo in SMEM, c=q*16+s (112 cols).
//   Hidden layer: D[j,c] = sum_i W[i,j]*S[i,c]; M=256, N=112, K=256.
//   3 passes Whi*Shi + Whi*Slo + Wlo*Shi accumulated in fp32 registers.
//   Thread (g,tg) owns rows g,g+8 of its 2 j-tiles and cols 2tg,2tg+1 of
//   every c-tile -> all 7 quantities of 4 samples are thread-local.
// ============================================================

#define THREADS 256
#define SB 16
#define CT 14                 // c-tiles of 8
#define BROW 240              // bytes per state row (112*2 = 224 + 16 pad)
#define BHALF (256 * BROW)    // 61440 per half

#define SM_BHI 0
#define SM_BLO BHALF
#define SM_W4   (2 * BHALF)         // 122880 : w4t[o][i] f32, 2048 B
#define SM_BIAS (SM_W4 + 2048)      // 124928 : b1,b2,b3 f32, 3072 B
#define SM_TOTAL (SM_BIAS + 3072)   // 128000
// final-layer fp32 state overlays BHI/BLO: S3f[c][i], row stride 1040 B
#define S3STRIDE 260                // floats per row (256 + 4 pad)

// pre-transposed weights: WtH/WtL[L][j][i] bf16, j,i in [0,256)
__device__ uint16_t g_WtH[3 * 256 * 256];
__device__ uint16_t g_WtL[3 * 256 * 256];

__device__ __forceinline__ uint32_t smem_u32(const void* p) {
    uint32_t a;
    asm("{ .reg .u64 t; cvta.to.shared.u64 t, %1; cvt.u32.u64 %0, t; }"
        : "=r"(a) : "l"(p));
    return a;
}
__device__ __forceinline__ void ldmB(uint32_t& b0, uint32_t& b1, uint32_t addr) {
    asm volatile("ldmatrix.sync.aligned.m8n8.x2.trans.shared.b16 {%0,%1}, [%2];"
                 : "=r"(b0), "=r"(b1) : "r"(addr));
}
__device__ __forceinline__ void mma16816(float* d, const uint32_t* a,
                                         uint32_t b0, uint32_t b1) {
    asm volatile(
        "mma.sync.aligned.m16n8k16.row.col.f32.bf16.bf16.f32 "
        "{%0,%1,%2,%3}, {%4,%5,%6,%7}, {%8,%9}, {%0,%1,%2,%3};"
        : "+f"(d[0]), "+f"(d[1]), "+f"(d[2]), "+f"(d[3])
        : "r"(a[0]), "r"(a[1]), "r"(a[2]), "r"(a[3]), "r"(b0), "r"(b1));
}
__device__ __forceinline__ uint32_t pk2(float a, float b) {
    return (uint32_t)__bfloat16_as_ushort(__float2bfloat16(a)) |
           ((uint32_t)__bfloat16_as_ushort(__float2bfloat16(b)) << 16);
}

// ---------------- prep: W[L] (i-major) -> Wt[L][j][i] bf16 hi/lo ----------
__global__ void __launch_bounds__(256) prep_kernel(
    const float* __restrict__ W1, const float* __restrict__ W2,
    const float* __restrict__ W3)
{
    int idx = blockIdx.x * 256 + threadIdx.x;   // = L*65536 + j*256 + i
    int L = idx >> 16;
    int j = (idx >> 8) & 255;
    int i = idx & 255;
    const float* W = (L == 0) ? W1 : ((L == 1) ? W2 : W3);
    float v = W[i * 256 + j];
    __nv_bfloat16 hb = __float2bfloat16(v);
    float lo = v - __bfloat162float(hb);
    g_WtH[idx] = __bfloat16_as_ushort(hb);
    g_WtL[idx] = __bfloat16_as_ushort(__float2bfloat16(lo));
}

// ---------------- main kernel ----------------
__global__ void __launch_bounds__(THREADS, 1) pinn_mma_kernel(
    const float* __restrict__ x,
    const float* __restrict__ W0, const float* __restrict__ b0_,
    const float* __restrict__ b1_, const float* __restrict__ b2_,
    const float* __restrict__ b3_,
    const float* __restrict__ W4, const float* __restrict__ b4,
    const float* __restrict__ lb, const float* __restrict__ ub,
    float* __restrict__ out, int N)
{
    extern __shared__ char sm[];
    const uint32_t smb = smem_u32(sm);
    const int tid  = threadIdx.x;
    const int warp = tid >> 5, lane = tid & 31;
    const int g = lane >> 2, tg = lane & 3;
    const int s0 = blockIdx.x * SB;

    // stage W4 transposed (w4t[o][i]) and hidden biases
    for (int i = tid; i < 512; i += THREADS)
        ((float*)(sm + SM_W4))[(i & 1) * 256 + (i >> 1)] = W4[i];
    {
        ((float*)(sm + SM_BIAS))[tid]       = b1_[tid];
        ((float*)(sm + SM_BIAS))[256 + tid] = b2_[tid];
        ((float*)(sm + SM_BIAS))[512 + tid] = b3_[tid];
    }

    // ---------- layer 0: 3 -> 256 (SIMT), write bf16 hi/lo state ----------
    {
        float lbv[3], sk[3];
#pragma unroll
        for (int k = 0; k < 3; k++) { lbv[k] = lb[k]; sk[k] = 2.0f / (ub[k] - lb[k]); }
        const int j = tid;
        float w[3];
#pragma unroll
        for (int k = 0; k < 3; k++) w[k] = W0[k * 256 + j];
        const float bj = b0_[j];
        float zj[3], Szl = 0.0f;
#pragma unroll
        for (int k = 0; k < 3; k++) { zj[k] = w[k] * sk[k]; Szl += zj[k]; }
#pragma unroll
        for (int sp = 0; sp < 8; sp++) {
            float v[2][7];
#pragma unroll
            for (int p = 0; p < 2; p++) {
                const int s = 2 * sp + p;
                float xn0 = sk[0] * (x[(s0 + s) * 3 + 0] - lbv[0]) - 1.0f;
                float xn1 = sk[1] * (x[(s0 + s) * 3 + 1] - lbv[1]) - 1.0f;
                float xn2 = sk[2] * (x[(s0 + s) * 3 + 2] - lbv[2]) - 1.0f;
                float z = bj + w[0] * xn0 + w[1] * xn1 + w[2] * xn2;
                float t = tanhf(z);
                float gg = 1.0f - t * t;
                float u = -2.0f * t * gg * Szl;
                v[p][0] = t;
#pragma unroll
                for (int k = 0; k < 3; k++) { v[p][1 + k] = gg * zj[k]; v[p][4 + k] = u * zj[k]; }
            }
#pragma unroll
            for (int q = 0; q < 7; q++) {
                const int off = j * BROW + 32 * q + 4 * sp;   // col = 16q + 2sp
                float h0 = __bfloat162float(__float2bfloat16(v[0][q]));
                float h1 = __bfloat162float(__float2bfloat16(v[1][q]));
                *(uint32_t*)(sm + SM_BHI + off) = pk2(v[0][q], v[1][q]);
                *(uint32_t*)(sm + SM_BLO + off) = pk2(v[0][q] - h0, v[1][q] - h1);
            }
        }
    }
    __syncthreads();

    // ---------- hidden layers 1..3 via mma.sync ----------
    const int jt0 = warp * 2;
    const uint32_t brow = (uint32_t)((lane & 15) * BROW);
#pragma unroll 1
    for (int L = 0; L < 3; L++) {
        const uint16_t* __restrict__ WH = g_WtH + L * 65536;
        const uint16_t* __restrict__ WL = g_WtL + L * 65536;

        float acc[2][CT][4];
#pragma unroll
        for (int jj = 0; jj < 2; jj++)
#pragma unroll
            for (int ct = 0; ct < CT; ct++)
#pragma unroll
                for (int d = 0; d < 4; d++) acc[jj][ct][d] = 0.0f;

#pragma unroll 1
        for (int kb = 0; kb < 8; kb++) {
            uint32_t aH[2][2][4], aL[2][2][4];
#pragma unroll
            for (int jj = 0; jj < 2; jj++) {
                const int jbase = (jt0 + jj) * 16;
#pragma unroll
                for (int kk = 0; kk < 2; kk++) {
                    const int i0 = (kb * 2 + kk) * 16 + 2 * tg;
                    const uint16_t* pH = WH + (jbase + g) * 256 + i0;
                    const uint16_t* pL = WL + (jbase + g) * 256 + i0;
                    aH[jj][kk][0] = *(const uint32_t*)(pH);
                    aH[jj][kk][1] = *(const uint32_t*)(pH + 8 * 256);
                    aH[jj][kk][2] = *(const uint32_t*)(pH + 8);
                    aH[jj][kk][3] = *(const uint32_t*)(pH + 8 * 256 + 8);
                    aL[jj][kk][0] = *(const uint32_t*)(pL);
                    aL[jj][kk][1] = *(const uint32_t*)(pL + 8 * 256);
                    aL[jj][kk][2] = *(const uint32_t*)(pL + 8);
                    aL[jj][kk][3] = *(const uint32_t*)(pL + 8 * 256 + 8);
                }
            }
#pragma unroll
            for (int ct = 0; ct < CT; ct++) {
#pragma unroll
                for (int kk = 0; kk < 2; kk++) {
                    const uint32_t baddr = smb + SM_BHI +
                        (uint32_t)((kb * 2 + kk) * 16 * BROW) + brow + ct * 16;
                    uint32_t bh0, bh1, bl0, bl1;
                    ldmB(bh0, bh1, baddr);
                    ldmB(bl0, bl1, baddr + BHALF);
#pragma unroll
                    for (int jj = 0; jj < 2; jj++) {
                        mma16816(acc[jj][ct], aH[jj][kk], bh0, bh1);
                        mma16816(acc[jj][ct], aH[jj][kk], bl0, bl1);
                        mma16816(acc[jj][ct], aL[jj][kk], bh0, bh1);
                    }
                }
            }
        }
        __syncthreads();   // all reads of old state done

        // ---------- elementwise (thread-local) ----------
        const float* bias = (const float*)(sm + SM_BIAS) + L * 256;
        const bool last = (L == 2);
#pragma unroll
        for (int jj = 0; jj < 2; jj++) {
#pragma unroll
            for (int r = 0; r < 2; r++) {
                const int j = (jt0 + jj) * 16 + g + 8 * r;
                const float bj = bias[j];
#pragma unroll
                for (int slp = 0; slp < 2; slp++) {
                    float v[2][7];
#pragma unroll
                    for (int p = 0; p < 2; p++) {
                        const int d = 2 * r + p;
                        float zh = acc[jj][slp][d] + bj;
                        float z0 = acc[jj][2 + slp][d];
                        float z1 = acc[jj][4 + slp][d];
                        float z2 = acc[jj][6 + slp][d];
                        float t0 = acc[jj][8 + slp][d];
                        float t1 = acc[jj][10 + slp][d];
                        float t2 = acc[jj][12 + slp][d];
                        float t = tanhf(zh);
                        float gg = 1.0f - t * t;
                        float Sz = z0 + z1 + z2;
                        float u = -2.0f * t * gg * Sz;
                        v[p][0] = t;
                        v[p][1] = gg * z0; v[p][2] = gg * z1; v[p][3] = gg * z2;
                        v[p][4] = u * z0 + gg * t0;
                        v[p][5] = u * z1 + gg * t1;
                        v[p][6] = u * z2 + gg * t2;
                    }
                    const int se = 2 * tg + 8 * slp;   // even sample index
                    if (!last) {
#pragma unroll
                        for (int q = 0; q < 7; q++) {
                            const int off = j * BROW + (16 * q + se) * 2;
                            float h0 = __bfloat162float(__float2bfloat16(v[0][q]));
                            float h1 = __bfloat162float(__float2bfloat16(v[1][q]));
                            *(uint32_t*)(sm + SM_BHI + off) = pk2(v[0][q], v[1][q]);
                            *(uint32_t*)(sm + SM_BLO + off) = pk2(v[0][q] - h0, v[1][q] - h1);
                        }
                    } else {
#pragma unroll
                        for (int q = 0; q < 7; q++) {
                            ((float*)sm)[(16 * q + se) * S3STRIDE + j]     = v[0][q];
                            ((float*)sm)[(16 * q + se + 1) * S3STRIDE + j] = v[1][q];
                        }
                    }
                }
            }
        }
        __syncthreads();
    }

    // ---------- final layer: 256 -> 2 ----------
    if (tid < 224) {
        const int o = tid & 1, c = tid >> 1;
        const float4* row = reinterpret_cast<const float4*>(sm + (size_t)c * (S3STRIDE * 4));
        const float4* wr  = reinterpret_cast<const float4*>(sm + SM_W4 + o * 1024);
        float sum = 0.0f;
#pragma unroll 8
        for (int i4 = 0; i4 < 64; i4++) {
            float4 a = row[i4];
            float4 b = wr[i4];
            sum += a.x * b.x + a.y * b.y + a.z * b.z + a.w * b.w;
        }
        const int q = c >> 4, s = c & 15;
        const int n = s0 + s;
        if (q == 0) {
            out[n * 2 + o] = sum + b4[o];
        } else if (q < 4) {
            out[2 * N + o * 3 * N + n * 3 + (q - 1)] = sum;
        } else {
            out[8 * N + o * 3 * N + n * 3 + (q - 4)] = sum;
        }
    }
}

extern "C" void kernel_launch(void* const* d_in, const int* in_sizes, int n_in,
                              void* d_out, int out_size)
{
    const float* x  = (const float*)d_in[0];
    const float* W0 = (const float*)d_in[1];
    const float* b0 = (const float*)d_in[2];
    const float* W1 = (const float*)d_in[3];
    const float* b1 = (const float*)d_in[4];
    const float* W2 = (const float*)d_in[5];
    const float* b2 = (const float*)d_in[6];
    const float* W3 = (const float*)d_in[7];
    const float* b3 = (const float*)d_in[8];
    const float* W4 = (const float*)d_in[9];
    const float* b4 = (const float*)d_in[10];
    const float* lb = (const float*)d_in[11];
    const float* ub = (const float*)d_in[12];
    float* out = (float*)d_out;

    const int N = in_sizes[0] / 3;          // 32768

    prep_kernel<<<3 * 256 * 256 / 256, 256>>>(W1, W2, W3);

    cudaFuncSetAttribute(pinn_mma_kernel,
                         cudaFuncAttributeMaxDynamicSharedMemorySize, SM_TOTAL);
    pinn_mma_kernel<<<N / SB, THREADS, SM_TOTAL>>>(
        x, W0, b0, b1, b2, b3, W4, b4, lb, ub, out, N);
}